// round 3
// baseline (speedup 1.0000x reference)
#include <cuda_runtime.h>
#include <cuda_bf16.h>
#include <cstdint>

#define N_NODES 100000
#define HEADS   8

// Per-(node, head) sum of exp(e). 100000*8 floats = 3.2 MB (L2-resident).
__device__ float g_sums[N_NODES * HEADS];

__global__ void zero_sums_kernel(int n4) {
    int i = blockIdx.x * blockDim.x + threadIdx.x;
    if (i < n4) reinterpret_cast<float4*>(g_sums)[i] = make_float4(0.f, 0.f, 0.f, 0.f);
}

__device__ __forceinline__ void exp8(float4& a, float4& b) {
    a.x = __expf(a.x); a.y = __expf(a.y); a.z = __expf(a.z); a.w = __expf(a.w);
    b.x = __expf(b.x); b.y = __expf(b.y); b.z = __expf(b.z); b.w = __expf(b.w);
}

// Pass 1: red-add exp(e) into g_sums[dst]. 4 edges per thread (forward order).
__global__ void scatter_sum_kernel(const float* __restrict__ e,
                                   const int* __restrict__ dst,
                                   int nGroups) {
    int g = blockIdx.x * blockDim.x + threadIdx.x;
    if (g >= nGroups) return;

    int4 d4 = reinterpret_cast<const int4*>(dst)[g];
    const float4* erow = reinterpret_cast<const float4*>(e) + (size_t)g * 8;

    // Front-batch all loads for MLP.
    float4 v[8];
#pragma unroll
    for (int k = 0; k < 8; k++) v[k] = erow[k];

    int ds[4] = {d4.x, d4.y, d4.z, d4.w};
#pragma unroll
    for (int k = 0; k < 4; k++) {
        float4 a = v[2 * k], b = v[2 * k + 1];
        exp8(a, b);
        float* srow = g_sums + (size_t)ds[k] * HEADS;
        asm volatile("red.global.add.v4.f32 [%0], {%1, %2, %3, %4};"
                     :: "l"(srow), "f"(a.x), "f"(a.y), "f"(a.z), "f"(a.w) : "memory");
        asm volatile("red.global.add.v4.f32 [%0], {%1, %2, %3, %4};"
                     :: "l"(srow + 4), "f"(b.x), "f"(b.y), "f"(b.z), "f"(b.w) : "memory");
    }
}

// Pass 2: out = exp(e) / (sums[dst] + eps). 4 edges per thread, REVERSE group
// order so pass-2 e reads start at the L2-resident tail left by pass 1.
__global__ void normalize_kernel(const float* __restrict__ e,
                                 const int* __restrict__ dst,
                                 float* __restrict__ out,
                                 int nGroups) {
    int j = blockIdx.x * blockDim.x + threadIdx.x;
    if (j >= nGroups) return;
    int g = nGroups - 1 - j;

    int4 d4 = __ldcs(reinterpret_cast<const int4*>(dst) + g);
    const float4* erow = reinterpret_cast<const float4*>(e) + (size_t)g * 8;

    float4 v[8];
#pragma unroll
    for (int k = 0; k < 8; k++) v[k] = __ldcs(erow + k);

    int ds[4] = {d4.x, d4.y, d4.z, d4.w};
    float4* orow = reinterpret_cast<float4*>(out) + (size_t)g * 8;
    const float eps = 1e-16f;

#pragma unroll
    for (int k = 0; k < 4; k++) {
        float4 a = v[2 * k], b = v[2 * k + 1];
        exp8(a, b);
        const float4* srow = reinterpret_cast<const float4*>(g_sums + (size_t)ds[k] * HEADS);
        float4 s0 = srow[0];
        float4 s1 = srow[1];
        float4 o0, o1;
        o0.x = a.x / (s0.x + eps); o0.y = a.y / (s0.y + eps);
        o0.z = a.z / (s0.z + eps); o0.w = a.w / (s0.w + eps);
        o1.x = b.x / (s1.x + eps); o1.y = b.y / (s1.y + eps);
        o1.z = b.z / (s1.z + eps); o1.w = b.w / (s1.w + eps);
        __stcs(orow + 2 * k, o0);
        __stcs(orow + 2 * k + 1, o1);
    }
}

// Scalar tail (only launched if E % 4 != 0; E = 3.2M so normally unused).
__global__ void tail_kernel(const float* __restrict__ e,
                            const int* __restrict__ dst,
                            float* __restrict__ out,
                            int start, int E, int phase) {
    int i = start + blockIdx.x * blockDim.x + threadIdx.x;
    if (i >= E) return;
    int d = dst[i];
    const float eps = 1e-16f;
    if (phase == 0) {
        for (int h = 0; h < HEADS; h++)
            atomicAdd(&g_sums[(size_t)d * HEADS + h], __expf(e[(size_t)i * HEADS + h]));
    } else {
        for (int h = 0; h < HEADS; h++) {
            float ex = __expf(e[(size_t)i * HEADS + h]);
            out[(size_t)i * HEADS + h] = ex / (g_sums[(size_t)d * HEADS + h] + eps);
        }
    }
}

extern "C" void kernel_launch(void* const* d_in, const int* in_sizes, int n_in,
                              void* d_out, int out_size) {
    const float* e = (const float*)d_in[0];
    const int* edge_index = (const int*)d_in[1];
    int E = in_sizes[0] / HEADS;
    const int* dst = edge_index + (size_t)E;  // edge_index[1]
    float* out = (float*)d_out;

    const int T = 256;
    int nGroups = E / 4;
    int rem = E % 4;

    zero_sums_kernel<<<(N_NODES * HEADS / 4 + T - 1) / T, T>>>(N_NODES * HEADS / 4);

    scatter_sum_kernel<<<(nGroups + T - 1) / T, T>>>(e, dst, nGroups);
    if (rem) tail_kernel<<<1, 32>>>(e, dst, out, nGroups * 4, E, 0);

    normalize_kernel<<<(nGroups + T - 1) / T, T>>>(e, dst, out, nGroups);
    if (rem) tail_kernel<<<1, 32>>>(e, dst, out, nGroups * 4, E, 1);
}

// round 4
// speedup vs baseline: 1.3682x; 1.3682x over previous
#include <cuda_runtime.h>
#include <cuda_bf16.h>
#include <cstdint>

#define N_NODES 100000
#define HEADS   8
#define UNROLL  4

// Per-(node, head) sum of exp(e). 100000*8 floats = 3.2 MB (L2-resident).
__device__ float g_sums[N_NODES * HEADS];

__global__ void zero_sums_kernel(int n4) {
    int i = blockIdx.x * blockDim.x + threadIdx.x;
    if (i < n4) reinterpret_cast<float4*>(g_sums)[i] = make_float4(0.f, 0.f, 0.f, 0.f);
}

__device__ __forceinline__ void exp8(float4& a, float4& b) {
    a.x = __expf(a.x); a.y = __expf(a.y); a.z = __expf(a.z); a.w = __expf(a.w);
    b.x = __expf(b.x); b.y = __expf(b.y); b.z = __expf(b.z); b.w = __expf(b.w);
}

// Pass 1: red-add exp(e) into g_sums[dst].
// Warp-strided 4-edge batching: edge i = base + k*blockDim.x keeps every
// individual load coalesced (lane stride = 1 edge) while giving MLP ~12.
__global__ void scatter_sum_kernel(const float* __restrict__ e,
                                   const int* __restrict__ dst,
                                   int E) {
    int base = blockIdx.x * (blockDim.x * UNROLL) + threadIdx.x;
    const float4* e4 = reinterpret_cast<const float4*>(e);

    int d[UNROLL];
    float4 va[UNROLL], vb[UNROLL];
#pragma unroll
    for (int k = 0; k < UNROLL; k++) {
        int i = base + k * blockDim.x;
        if (i < E) {
            d[k]  = dst[i];
            va[k] = e4[(size_t)i * 2];
            vb[k] = e4[(size_t)i * 2 + 1];
        }
    }
#pragma unroll
    for (int k = 0; k < UNROLL; k++) {
        int i = base + k * blockDim.x;
        if (i < E) {
            float4 a = va[k], b = vb[k];
            exp8(a, b);
            float* srow = g_sums + (size_t)d[k] * HEADS;
            asm volatile("red.global.add.v4.f32 [%0], {%1, %2, %3, %4};"
                         :: "l"(srow), "f"(a.x), "f"(a.y), "f"(a.z), "f"(a.w) : "memory");
            asm volatile("red.global.add.v4.f32 [%0], {%1, %2, %3, %4};"
                         :: "l"(srow + 4), "f"(b.x), "f"(b.y), "f"(b.z), "f"(b.w) : "memory");
        }
    }
}

// Pass 2: out = exp(e) / (sums[dst] + eps). Same batching; block order is
// REVERSED so early blocks read the L2-resident tail left by pass 1.
__global__ void normalize_kernel(const float* __restrict__ e,
                                 const int* __restrict__ dst,
                                 float* __restrict__ out,
                                 int E, int nBlocks) {
    int rb = nBlocks - 1 - blockIdx.x;
    int base = rb * ((int)blockDim.x * UNROLL) + threadIdx.x;
    const float4* e4 = reinterpret_cast<const float4*>(e);
    float4* o4 = reinterpret_cast<float4*>(out);

    int d[UNROLL];
    float4 va[UNROLL], vb[UNROLL];
#pragma unroll
    for (int k = 0; k < UNROLL; k++) {
        int i = base + k * blockDim.x;
        if (i < E) {
            d[k]  = __ldcs(dst + i);
            va[k] = __ldcs(e4 + (size_t)i * 2);
            vb[k] = __ldcs(e4 + (size_t)i * 2 + 1);
        }
    }
    const float eps = 1e-16f;
#pragma unroll
    for (int k = 0; k < UNROLL; k++) {
        int i = base + k * blockDim.x;
        if (i < E) {
            float4 a = va[k], b = vb[k];
            exp8(a, b);
            const float4* srow = reinterpret_cast<const float4*>(g_sums + (size_t)d[k] * HEADS);
            float4 s0 = srow[0];
            float4 s1 = srow[1];
            float4 o0, o1;
            o0.x = a.x / (s0.x + eps); o0.y = a.y / (s0.y + eps);
            o0.z = a.z / (s0.z + eps); o0.w = a.w / (s0.w + eps);
            o1.x = b.x / (s1.x + eps); o1.y = b.y / (s1.y + eps);
            o1.z = b.z / (s1.z + eps); o1.w = b.w / (s1.w + eps);
            __stcs(o4 + (size_t)i * 2, o0);
            __stcs(o4 + (size_t)i * 2 + 1, o1);
        }
    }
}

extern "C" void kernel_launch(void* const* d_in, const int* in_sizes, int n_in,
                              void* d_out, int out_size) {
    const float* e = (const float*)d_in[0];
    const int* edge_index = (const int*)d_in[1];
    int E = in_sizes[0] / HEADS;
    const int* dst = edge_index + (size_t)E;  // edge_index[1]
    float* out = (float*)d_out;

    const int T = 256;
    int perBlock = T * UNROLL;
    int nBlocks = (E + perBlock - 1) / perBlock;

    zero_sums_kernel<<<(N_NODES * HEADS / 4 + T - 1) / T, T>>>(N_NODES * HEADS / 4);
    scatter_sum_kernel<<<nBlocks, T>>>(e, dst, E);
    normalize_kernel<<<nBlocks, T>>>(e, dst, out, E, nBlocks);
}

// round 6
// speedup vs baseline: 1.5435x; 1.1281x over previous
#include <cuda_runtime.h>
#include <cuda_bf16.h>
#include <cstdint>

#define N_NODES 100000
#define HEADS   8
#define UNROLL  4

// Per-(node, head) sum of exp(e). 100000*8 floats = 3.2 MB (L2-resident).
__device__ float g_sums[N_NODES * HEADS];

__global__ void zero_sums_kernel(int n4) {
    int i = blockIdx.x * blockDim.x + threadIdx.x;
    if (i < n4) reinterpret_cast<float4*>(g_sums)[i] = make_float4(0.f, 0.f, 0.f, 0.f);
}

__device__ __forceinline__ void exp8(float4& a, float4& b) {
    a.x = __expf(a.x); a.y = __expf(a.y); a.z = __expf(a.z); a.w = __expf(a.w);
    b.x = __expf(b.x); b.y = __expf(b.y); b.z = __expf(b.z); b.w = __expf(b.w);
}

// 256-bit load with L2 evict_last (pin streamed array in L2 for pass 2).
__device__ __forceinline__ void ld256_evict_last(const float* p, float4& a, float4& b) {
    uint32_t r0, r1, r2, r3, r4, r5, r6, r7;
    asm volatile("ld.global.L2::evict_last.v8.b32 {%0,%1,%2,%3,%4,%5,%6,%7}, [%8];"
                 : "=r"(r0), "=r"(r1), "=r"(r2), "=r"(r3),
                   "=r"(r4), "=r"(r5), "=r"(r6), "=r"(r7)
                 : "l"(p));
    a.x = __uint_as_float(r0); a.y = __uint_as_float(r1);
    a.z = __uint_as_float(r2); a.w = __uint_as_float(r3);
    b.x = __uint_as_float(r4); b.y = __uint_as_float(r5);
    b.z = __uint_as_float(r6); b.w = __uint_as_float(r7);
}

// 256-bit streaming load (pass 2 read of e; may hit the pinned lines).
__device__ __forceinline__ void ld256_cs(const float* p, float4& a, float4& b) {
    uint32_t r0, r1, r2, r3, r4, r5, r6, r7;
    asm volatile("ld.global.cs.v8.b32 {%0,%1,%2,%3,%4,%5,%6,%7}, [%8];"
                 : "=r"(r0), "=r"(r1), "=r"(r2), "=r"(r3),
                   "=r"(r4), "=r"(r5), "=r"(r6), "=r"(r7)
                 : "l"(p));
    a.x = __uint_as_float(r0); a.y = __uint_as_float(r1);
    a.z = __uint_as_float(r2); a.w = __uint_as_float(r3);
    b.x = __uint_as_float(r4); b.y = __uint_as_float(r5);
    b.z = __uint_as_float(r6); b.w = __uint_as_float(r7);
}

// 256-bit store with L2 evict_first (streaming output, don't displace e).
__device__ __forceinline__ void st256_evict_first(float* p, float4 a, float4 b) {
    asm volatile("st.global.L2::evict_first.v8.b32 [%0], {%1,%2,%3,%4,%5,%6,%7,%8};"
                 :: "l"(p),
                    "r"(__float_as_uint(a.x)), "r"(__float_as_uint(a.y)),
                    "r"(__float_as_uint(a.z)), "r"(__float_as_uint(a.w)),
                    "r"(__float_as_uint(b.x)), "r"(__float_as_uint(b.y)),
                    "r"(__float_as_uint(b.z)), "r"(__float_as_uint(b.w))
                 : "memory");
}

// Pass 1: red-add exp(e) into g_sums[dst]. Warp-strided 4-edge batching.
__global__ void scatter_sum_kernel(const float* __restrict__ e,
                                   const int* __restrict__ dst,
                                   int E) {
    int base = blockIdx.x * (blockDim.x * UNROLL) + threadIdx.x;

    int d[UNROLL];
    float4 va[UNROLL], vb[UNROLL];
#pragma unroll
    for (int k = 0; k < UNROLL; k++) {
        int i = base + k * blockDim.x;
        if (i < E) {
            d[k] = __ldcs(dst + i);
            ld256_evict_last(e + (size_t)i * HEADS, va[k], vb[k]);
        }
    }
#pragma unroll
    for (int k = 0; k < UNROLL; k++) {
        int i = base + k * blockDim.x;
        if (i < E) {
            float4 a = va[k], b = vb[k];
            exp8(a, b);
            float* srow = g_sums + (size_t)d[k] * HEADS;
            asm volatile("red.global.add.v4.f32 [%0], {%1, %2, %3, %4};"
                         :: "l"(srow), "f"(a.x), "f"(a.y), "f"(a.z), "f"(a.w) : "memory");
            asm volatile("red.global.add.v4.f32 [%0], {%1, %2, %3, %4};"
                         :: "l"(srow + 4), "f"(b.x), "f"(b.y), "f"(b.z), "f"(b.w) : "memory");
        }
    }
}

// Pass 2: out = exp(e) * fast_rcp(sums[dst] + eps). Reverse block order so the
// earliest pass-2 reads hit the L2-resident tail of e left by pass 1.
__global__ void normalize_kernel(const float* __restrict__ e,
                                 const int* __restrict__ dst,
                                 float* __restrict__ out,
                                 int E, int nBlocks) {
    int rb = nBlocks - 1 - blockIdx.x;
    int base = rb * ((int)blockDim.x * UNROLL) + threadIdx.x;

    int d[UNROLL];
    float4 va[UNROLL], vb[UNROLL];
#pragma unroll
    for (int k = 0; k < UNROLL; k++) {
        int i = base + k * blockDim.x;
        if (i < E) {
            d[k] = __ldcs(dst + i);
            ld256_cs(e + (size_t)i * HEADS, va[k], vb[k]);
        }
    }
    const float eps = 1e-16f;
#pragma unroll
    for (int k = 0; k < UNROLL; k++) {
        int i = base + k * blockDim.x;
        if (i < E) {
            float4 a = va[k], b = vb[k];
            exp8(a, b);
            const float4* srow = reinterpret_cast<const float4*>(g_sums + (size_t)d[k] * HEADS);
            float4 s0 = srow[0];
            float4 s1 = srow[1];
            float4 o0, o1;
            o0.x = __fdividef(a.x, s0.x + eps); o0.y = __fdividef(a.y, s0.y + eps);
            o0.z = __fdividef(a.z, s0.z + eps); o0.w = __fdividef(a.w, s0.w + eps);
            o1.x = __fdividef(b.x, s1.x + eps); o1.y = __fdividef(b.y, s1.y + eps);
            o1.z = __fdividef(b.z, s1.z + eps); o1.w = __fdividef(b.w, s1.w + eps);
            st256_evict_first(out + (size_t)i * HEADS, o0, o1);
        }
    }
}

extern "C" void kernel_launch(void* const* d_in, const int* in_sizes, int n_in,
                              void* d_out, int out_size) {
    const float* e = (const float*)d_in[0];
    const int* edge_index = (const int*)d_in[1];
    int E = in_sizes[0] / HEADS;
    const int* dst = edge_index + (size_t)E;  // edge_index[1]
    float* out = (float*)d_out;

    const int T = 256;
    int perBlock = T * UNROLL;
    int nBlocks = (E + perBlock - 1) / perBlock;

    zero_sums_kernel<<<(N_NODES * HEADS / 4 + T - 1) / T, T>>>(N_NODES * HEADS / 4);
    scatter_sum_kernel<<<nBlocks, T>>>(e, dst, E);
    normalize_kernel<<<nBlocks, T>>>(e, dst, out, E, nBlocks);
}